// round 5
// baseline (speedup 1.0000x reference)
#include <cuda_runtime.h>
#include <math.h>

#define Bb 64
#define Tt 2048
#define Vv 256
#define Uu 256
#define NEGV (-1e30f)
#define NCHUNK 32            // 64-row gather chunks per batch

__device__ float g_d[(size_t)Bb * Tt * 256];   // d[b,t,i] = logits[b,t,tgt[i]] - logits[b,t,0]
__device__ float g_Cpart[Bb * 256];            // per-8-row blank-logp partials (never-written = 0)
__device__ float g_nll[Bb];
__device__ int   g_flags[Bb * NCHUNK];         // chunk-ready flags (cleared by finalize)

__device__ __forceinline__ void cp16(unsigned sa, const float* g) {
    asm volatile("cp.async.cg.shared.global [%0], [%1], 16;\n" :: "r"(sa), "l"(g) : "memory");
}
__device__ __forceinline__ void cpcommit() {
    asm volatile("cp.async.commit_group;\n" ::: "memory");
}
template<int N> __device__ __forceinline__ void cpwait() {
    asm volatile("cp.async.wait_group %0;\n" :: "n"(N) : "memory");
}
__device__ __forceinline__ void waitflag(const int* p) {
    int f;
    while (true) {
        asm volatile("ld.acquire.gpu.global.b32 %0, [%1];" : "=r"(f) : "l"(p) : "memory");
        if (f) break;
        __nanosleep(128);
    }
}

// ===========================================================================
// Fat kernel: blocks 0..7 = DP (8 warps, one batch each); blocks 8.. = gather.
// ===========================================================================
__global__ void __launch_bounds__(256, 2) fat_kernel(const float* __restrict__ logits,
                                                     const int*  __restrict__ targets,
                                                     const int*  __restrict__ loglen,
                                                     const int*  __restrict__ tgtlen) {
    // union: gather uses [0,1KB) sTgt + [1KB,33KB) sRow[8][4][256]
    //        dp uses per-warp 2112B output scratch
    __shared__ char uSmem[34 * 1024];

    const int tid  = threadIdx.x;
    const int wid  = tid >> 5;
    const int lane = tid & 31;

    if (blockIdx.x >= 8) {
        // ------------------------------------------------------------------
        // GATHER role: chunk-major ordering (all batches' chunk c together)
        // ------------------------------------------------------------------
        const int g  = blockIdx.x - 8;
        const int b  = g & (Bb - 1);
        const int c  = g >> 6;
        const int L  = loglen[b];
        const int t0 = c * 64;
        if (t0 >= L) return;                       // whole block: no flag needed

        int*   sTgt = (int*)uSmem;
        float* sRow = (float*)(uSmem + 1024) + wid * (4 * Vv);

        sTgt[tid] = targets[b * Uu + tid];
        __syncthreads();

        const int tbase = t0 + wid * 8;
        int nrows = L - tbase; if (nrows > 8) nrows = 8; if (nrows < 0) nrows = 0;

        if (nrows > 0) {
            const float* lg   = logits + ((size_t)b * Tt + tbase) * Vv;
            float*       dOut = g_d    + ((size_t)b * Tt + tbase) * 256;

#pragma unroll
            for (int p = 0; p < 3; ++p) {
                if (p < nrows) {
                    unsigned sa = (unsigned)__cvta_generic_to_shared(&sRow[p * Vv + lane * 8]);
                    const float* gp = lg + (size_t)p * Vv + lane * 8;
                    cp16(sa, gp);
                    cp16(sa + 16, gp + 4);
                }
                cpcommit();
            }

            float cb = 0.0f;
            for (int k = 0; k < nrows; ++k) {
                int pf = k + 3;
                if (pf < nrows) {
                    unsigned sa = (unsigned)__cvta_generic_to_shared(&sRow[(pf & 3) * Vv + lane * 8]);
                    const float* gp = lg + (size_t)pf * Vv + lane * 8;
                    cp16(sa, gp);
                    cp16(sa + 16, gp + 4);
                }
                cpcommit();
                cpwait<3>();
                __syncwarp();

                const float* r = &sRow[(k & 3) * Vv];
                float4 v0 = *(const float4*)&r[lane * 4];
                float4 v1 = *(const float4*)&r[128 + lane * 4];
                float s = __expf(v0.x) + __expf(v0.y) + __expf(v0.z) + __expf(v0.w)
                        + __expf(v1.x) + __expf(v1.y) + __expf(v1.z) + __expf(v1.w);
#pragma unroll
                for (int o = 16; o; o >>= 1) s += __shfl_xor_sync(0xffffffffu, s, o);
                float lse = __logf(s);
                float r0  = __shfl_sync(0xffffffffu, v0.x, 0);
                cb += r0 - lse;

                int4 tg0 = *(const int4*)&sTgt[lane * 8];
                int4 tg1 = *(const int4*)&sTgt[lane * 8 + 4];
                float4 d0, d1;
                d0.x = r[tg0.x] - r0;  d0.y = r[tg0.y] - r0;
                d0.z = r[tg0.z] - r0;  d0.w = r[tg0.w] - r0;
                d1.x = r[tg1.x] - r0;  d1.y = r[tg1.y] - r0;
                d1.z = r[tg1.z] - r0;  d1.w = r[tg1.w] - r0;

                *(float4*)&dOut[(size_t)k * 256 + lane * 8]     = d0;
                *(float4*)&dOut[(size_t)k * 256 + lane * 8 + 4] = d1;
                __syncwarp();
            }
            if (lane == 0) g_Cpart[b * 256 + (tbase >> 3)] = cb;
        }

        __syncthreads();                            // all warps' STGs done
        if (tid == 0) {
            __threadfence();
            asm volatile("st.release.gpu.global.b32 [%0], %1;"
                         :: "l"(&g_flags[b * NCHUNK + c]), "r"(1) : "memory");
        }
        return;
    }

    // ----------------------------------------------------------------------
    // DP role: warp wid of block d handles batch d*8+wid. 2 warps per SMSP.
    // Pair i: E_i = alpha[2i], O_i = alpha[2i+1]; lane owns 8 pairs.
    //   E' = max(E, pO);  O' = max(O, E, pO+gate) + d
    // d streamed through a register ring (8 rows x 8 floats), LDG 8 steps ahead.
    // ----------------------------------------------------------------------
    const int b    = blockIdx.x * 8 + wid;
    const int L    = loglen[b];
    const int Ut   = tgtlen[b];
    const float* __restrict__ emB = g_d + (size_t)b * Tt * 256;
    const int ibase = lane * 8;
    const int* flagB = &g_flags[b * NCHUNK];

    float gate[8];
    {
        int prev = (lane == 0) ? -1 : targets[b * Uu + ibase - 1];
#pragma unroll
        for (int j = 0; j < 8; ++j) {
            int cur = targets[b * Uu + ibase + j];
            gate[j] = (ibase + j >= 1 && cur != prev) ? 0.0f : NEGV;
            prev = cur;
        }
    }
    const float pOmask = (lane == 0) ? NEGV : 0.0f;

    float E[8], O[8];
#pragma unroll
    for (int j = 0; j < 8; ++j) { E[j] = NEGV; O[j] = NEGV; }
    float Eex = NEGV;
    if (lane == 0) E[0] = 0.0f;
    float pO_cur = NEGV;

    float buf[8][8];

    waitflag(&flagB[0]);
    // preload rows 0..7 (L >= 1024 so all exist)
#pragma unroll
    for (int p = 0; p < 8; ++p) {
        const float4* gp = (const float4*)(emB + (size_t)p * 256 + ibase);
        *(float4*)&buf[p][0] = __ldg(gp);
        *(float4*)&buf[p][4] = __ldg(gp + 1);
    }

#define SUBSTEP(U, T)                                                         \
    {                                                                         \
        float e7 = E[7], o7 = O[7];                                           \
        float O7n = fmaxf(fmaxf(o7, e7), O[6] + gate[7]) + buf[U][7];         \
        float E7n = fmaxf(e7, O[6]);                                          \
        float nextPO = __shfl_up_sync(0xffffffffu, O7n, 1);                   \
        float pO = pO_cur;                                                    \
        _Pragma("unroll")                                                     \
        for (int j = 0; j < 7; ++j) {                                         \
            float e = E[j], o = O[j];                                         \
            E[j] = fmaxf(e, pO);                                              \
            O[j] = fmaxf(fmaxf(o, e), pO + gate[j]) + buf[U][j];              \
            pO = o;                                                           \
        }                                                                     \
        Eex = fmaxf(Eex, o7);                                                 \
        E[7] = E7n; O[7] = O7n;                                               \
        pO_cur = nextPO + pOmask;                                             \
        int pr_ = (T) + 8; if (pr_ > Tt - 1) pr_ = Tt - 1;                    \
        const float4* gp_ = (const float4*)(emB + (size_t)pr_ * 256 + ibase); \
        *(float4*)&buf[U][0] = __ldg(gp_);                                    \
        *(float4*)&buf[U][4] = __ldg(gp_ + 1);                                \
    }

    const int nchunk = (L + 63) >> 6;
    int t = 0;
    for (int c = 0; c < nchunk; ++c) {
        if ((c + 1) * 64 < L) waitflag(&flagB[c + 1]);   // prefetches cross into c+1
        const int lim = (L - c * 64 >= 64) ? 64 : (L - c * 64);
        if (lim == 64) {
            for (int gq = 0; gq < 8; ++gq) {
#pragma unroll
                for (int u = 0; u < 8; ++u) { SUBSTEP(u, t + u); }
                t += 8;
            }
        } else {
            for (int gq = 0; gq < 8; ++gq) {
                const int base = gq * 8;
#pragma unroll
                for (int u = 0; u < 8; ++u) {
                    if (base + u < lim) { SUBSTEP(u, t + u); }
                }
                t += 8;
                if (base + 8 >= lim) break;
            }
        }
    }
#undef SUBSTEP

    // fold in blank-logp sum C_b (fixed order -> deterministic)
    float Cacc = 0.0f;
#pragma unroll
    for (int j = 0; j < 8; ++j) Cacc += g_Cpart[b * 256 + ibase + j];
#pragma unroll
    for (int o2 = 16; o2; o2 >>= 1) Cacc += __shfl_xor_sync(0xffffffffu, Cacc, o2);

    float* sE = (float*)(uSmem + wid * 2112);
    float* sO = sE + 257;
#pragma unroll
    for (int j = 0; j < 8; ++j) { sE[ibase + j] = E[j]; sO[ibase + j] = O[j]; }
    if (lane == 31) sE[256] = Eex;
    __syncwarp();
    if (lane == 0) {
        float vb = sE[Ut];
        float vl = sO[Ut - 1];
        g_nll[b] = -(fmaxf(vb, vl) + Cacc);
    }
}

// ===========================================================================
// Finalize: reduce to scalar loss AND clear flags for the next launch.
// ===========================================================================
__global__ void __launch_bounds__(256) finalize_kernel(const int* __restrict__ loglen,
                                                       float* __restrict__ out) {
    int tid = threadIdx.x;
    for (int i = tid; i < Bb * NCHUNK; i += 256) g_flags[i] = 0;
    if (tid < 32) {
        float s = 0.0f, c = 0.0f;
        for (int bb = tid; bb < Bb; bb += 32) { s += g_nll[bb]; c += (float)loglen[bb]; }
#pragma unroll
        for (int o = 16; o; o >>= 1) {
            s += __shfl_xor_sync(0xffffffffu, s, o);
            c += __shfl_xor_sync(0xffffffffu, c, o);
        }
        if (tid == 0) out[0] = s / c;
    }
}

// ===========================================================================
extern "C" void kernel_launch(void* const* d_in, const int* in_sizes, int n_in,
                              void* d_out, int out_size) {
    const float* logits  = (const float*)d_in[0];
    const int*   targets = (const int*)d_in[1];
    const int*   loglen  = (const int*)d_in[2];
    const int*   tgtlen  = (const int*)d_in[3];

    fat_kernel<<<8 + Bb * NCHUNK, 256>>>(logits, targets, loglen, tgtlen);
    finalize_kernel<<<1, 256>>>(loglen, (float*)d_out);
}

// round 6
// speedup vs baseline: 1.6478x; 1.6478x over previous
#include <cuda_runtime.h>
#include <math.h>

#define Bb 64
#define Tt 2048
#define Vv 256
#define Uu 256
#define NEGV (-1e30f)

__device__ float g_d[(size_t)Bb * Tt * 256];   // d[b,t,i] = logits[b,t,tgt[i]] - logits[b,t,0]
__device__ float g_Cpart[Bb * 256];            // per-8-row blank-logp partials
__device__ float g_nll[Bb];

__device__ __forceinline__ void cp16(unsigned sa, const float* g) {
    asm volatile("cp.async.cg.shared.global [%0], [%1], 16;\n" :: "r"(sa), "l"(g) : "memory");
}
__device__ __forceinline__ void cpcommit() {
    asm volatile("cp.async.commit_group;\n" ::: "memory");
}
template<int N> __device__ __forceinline__ void cpwait() {
    asm volatile("cp.async.wait_group %0;\n" :: "n"(N) : "memory");
}

// ---------------------------------------------------------------------------
// Kernel 1: fused lse + emission-delta gather + blank-logp partial sums.
// (identical to the 125.7us R4 version: 37.8us, DRAM 50%)
// ---------------------------------------------------------------------------
#define GB_ROWS 64
__global__ void __launch_bounds__(256) gather_kernel(const float* __restrict__ logits,
                                                     const int*  __restrict__ targets,
                                                     const int*  __restrict__ loglen) {
    __shared__ int   sTgt[Uu];
    __shared__ float sRow[8][4][Vv];

    const int b  = blockIdx.y;
    const int c  = blockIdx.x;
    const int L  = loglen[b];
    const int t0 = c * GB_ROWS;
    if (t0 >= L) return;

    const int tid = threadIdx.x, w = tid >> 5, lane = tid & 31;
    sTgt[tid] = targets[b * Uu + tid];
    __syncthreads();

    const int tbase = t0 + w * 8;
    if (tbase >= L) return;
    int nrows = L - tbase; if (nrows > 8) nrows = 8;

    const float* lg   = logits + ((size_t)b * Tt + tbase) * Vv;
    float*       dOut = g_d    + ((size_t)b * Tt + tbase) * 256;

#pragma unroll
    for (int p = 0; p < 3; ++p) {
        if (p < nrows) {
            unsigned sa = (unsigned)__cvta_generic_to_shared(&sRow[w][p][lane * 8]);
            const float* g = lg + (size_t)p * Vv + lane * 8;
            cp16(sa, g);
            cp16(sa + 16, g + 4);
        }
        cpcommit();
    }

    float cb = 0.0f;
    for (int k = 0; k < nrows; ++k) {
        int pf = k + 3;
        if (pf < nrows) {
            unsigned sa = (unsigned)__cvta_generic_to_shared(&sRow[w][pf & 3][lane * 8]);
            const float* g = lg + (size_t)pf * Vv + lane * 8;
            cp16(sa, g);
            cp16(sa + 16, g + 4);
        }
        cpcommit();
        cpwait<3>();
        __syncwarp();

        const float* r = sRow[w][k & 3];
        float4 v0 = *(const float4*)&r[lane * 4];
        float4 v1 = *(const float4*)&r[128 + lane * 4];
        float s = __expf(v0.x) + __expf(v0.y) + __expf(v0.z) + __expf(v0.w)
                + __expf(v1.x) + __expf(v1.y) + __expf(v1.z) + __expf(v1.w);
#pragma unroll
        for (int o = 16; o; o >>= 1) s += __shfl_xor_sync(0xffffffffu, s, o);
        float lse = __logf(s);
        float r0  = __shfl_sync(0xffffffffu, v0.x, 0);
        cb += r0 - lse;

        int4 tg0 = *(const int4*)&sTgt[lane * 8];
        int4 tg1 = *(const int4*)&sTgt[lane * 8 + 4];
        float4 d0, d1;
        d0.x = r[tg0.x] - r0;  d0.y = r[tg0.y] - r0;
        d0.z = r[tg0.z] - r0;  d0.w = r[tg0.w] - r0;
        d1.x = r[tg1.x] - r0;  d1.y = r[tg1.y] - r0;
        d1.z = r[tg1.z] - r0;  d1.w = r[tg1.w] - r0;

        *(float4*)&dOut[(size_t)k * 256 + lane * 8]     = d0;
        *(float4*)&dOut[(size_t)k * 256 + lane * 8 + 4] = d1;
        __syncwarp();
    }
    if (lane == 0) g_Cpart[b * 256 + (tbase >> 3)] = cb;
}

// ---------------------------------------------------------------------------
// Kernel 2: barrier-free Viterbi DP. 8 blocks x 8 warps: warp w -> batch
// blockIdx*8+w, so each SMSP co-schedules 2 independent recurrences (warps
// w and w+4), filling dependency-stall gaps. Per-warp 16-row cp.async ring
// in dynamic smem (issue-after-consume: group blk+4 overwrites group blk's
// slots only after block blk is consumed). Early-shuffle step as in R4.
// ---------------------------------------------------------------------------
#define DPG 4
#define DROWS 16
#define RINGF (DROWS * 256)          // floats per warp ring
__global__ void __launch_bounds__(256, 1) dp_kernel(const int* __restrict__ targets,
                                                    const int* __restrict__ loglen,
                                                    const int* __restrict__ tgtlen) {
    extern __shared__ float sDyn[];

    const int tid  = threadIdx.x;
    const int wid  = tid >> 5;
    const int lane = tid & 31;
    const int b    = blockIdx.x * 8 + wid;
    const int L    = loglen[b];
    const int Ut   = tgtlen[b];
    const float* emB = g_d + (size_t)b * Tt * 256;
    const int ibase = lane * 8;

    float* ring = sDyn + wid * RINGF;
    const unsigned sdBase = (unsigned)__cvta_generic_to_shared(ring);

    float gate[8];
    {
        int prev = (lane == 0) ? -1 : targets[b * Uu + ibase - 1];
#pragma unroll
        for (int j = 0; j < 8; ++j) {
            int cur = targets[b * Uu + ibase + j];
            gate[j] = (ibase + j >= 1 && cur != prev) ? 0.0f : NEGV;
            prev = cur;
        }
    }
    const float pOmask = (lane == 0) ? NEGV : 0.0f;

    float E[8], O[8];
#pragma unroll
    for (int j = 0; j < 8; ++j) { E[j] = NEGV; O[j] = NEGV; }
    float Eex = NEGV;
    if (lane == 0) E[0] = 0.0f;   // alpha_hat seed
    float pO_cur = NEGV;

#define ISSUE4U(ROW0)                                                         \
    {                                                                         \
        _Pragma("unroll")                                                     \
        for (int r_ = 0; r_ < 4; ++r_) {                                      \
            int row_ = (ROW0) + r_;                                           \
            unsigned sa_ = sdBase + ((((unsigned)row_ & (DROWS-1u)) << 8) + ibase) * 4u; \
            const float* g_ = emB + (size_t)row_ * 256 + ibase;               \
            cp16(sa_, g_);                                                    \
            cp16(sa_ + 16, g_ + 4);                                           \
        }                                                                     \
        cpcommit();                                                           \
    }
#define ISSUE4G(ROW0)                                                         \
    {                                                                         \
        _Pragma("unroll")                                                     \
        for (int r_ = 0; r_ < 4; ++r_) {                                      \
            int row_ = (ROW0) + r_;                                           \
            if (row_ < L) {                                                   \
                unsigned sa_ = sdBase + ((((unsigned)row_ & (DROWS-1u)) << 8) + ibase) * 4u; \
                const float* g_ = emB + (size_t)row_ * 256 + ibase;           \
                cp16(sa_, g_);                                                \
                cp16(sa_ + 16, g_ + 4);                                       \
            }                                                                 \
        }                                                                     \
        cpcommit();                                                           \
    }

    // prologue: groups 0..3 (rows 0..15; L >= 1024 so all valid)
#pragma unroll
    for (int g2 = 0; g2 < DPG; ++g2) ISSUE4U(g2 * 4);
    cpwait<DPG - 2>();                 // groups 0,1 resident

    float buf[2][8];
    {
        const float* sp = ring + ibase;
        *(float4*)&buf[0][0] = *(const float4*)sp;
        *(float4*)&buf[0][4] = *(const float4*)(sp + 4);
    }

    const int nblk = L >> 2;
    const int rem  = L & 3;

#define SUBSTEP(KPAR, T)                                                      \
    {                                                                         \
        const float* sp_ = ring + ((((T) + 1) & (DROWS-1)) << 8) + ibase;     \
        *(float4*)&buf[((KPAR) + 1) & 1][0] = *(const float4*)sp_;            \
        *(float4*)&buf[((KPAR) + 1) & 1][4] = *(const float4*)(sp_ + 4);      \
        const float* dv = buf[(KPAR) & 1];                                    \
        float e7 = E[7], o7 = O[7];                                           \
        float O7n = fmaxf(fmaxf(o7, e7), O[6] + gate[7]) + dv[7];             \
        float E7n = fmaxf(e7, O[6]);                                          \
        float nextPO = __shfl_up_sync(0xffffffffu, O7n, 1);                   \
        float pO = pO_cur;                                                    \
        _Pragma("unroll")                                                     \
        for (int j = 0; j < 7; ++j) {                                         \
            float e = E[j], o = O[j];                                         \
            E[j] = fmaxf(e, pO);                                              \
            O[j] = fmaxf(fmaxf(o, e), pO + gate[j]) + dv[j];                  \
            pO = o;                                                           \
        }                                                                     \
        Eex = fmaxf(Eex, o7);                                                 \
        E[7] = E7n; O[7] = O7n;                                               \
        pO_cur = nextPO + pOmask;                                             \
    }

    // consume block blk, THEN issue group blk+DPG (its slots alias block blk)
    const int nfast = nblk - DPG;
    int blk = 0;
    for (; blk < nfast; ++blk) {
        cpwait<DPG - 2>();             // block blk (and blk+1's first rows) resident
        const int t0 = blk * 4;
#pragma unroll
        for (int k = 0; k < 4; ++k) { SUBSTEP(k, t0 + k); }
        ISSUE4U((blk + DPG) * 4);
    }
    for (; blk < nblk; ++blk) {
        cpwait<DPG - 2>();
        const int t0 = blk * 4;
#pragma unroll
        for (int k = 0; k < 4; ++k) { SUBSTEP(k, t0 + k); }
        ISSUE4G((blk + DPG) * 4);
    }

    // tail (<= 3 steps)
    cpwait<0>();
#pragma unroll
    for (int k = 0; k < 3; ++k) {
        if (k < rem) { SUBSTEP(k, nblk * 4 + k); }
    }

    // fold in blank-logp sum C_b (fixed order -> deterministic)
    float Cacc = 0.0f;
#pragma unroll
    for (int j = 0; j < 8; ++j) Cacc += g_Cpart[b * 256 + ibase + j];
#pragma unroll
    for (int o2 = 16; o2; o2 >>= 1) Cacc += __shfl_xor_sync(0xffffffffu, Cacc, o2);

    // reuse own ring region as epilogue scratch (ring is dead now)
    float* sE = ring;
    float* sO = ring + 257;
#pragma unroll
    for (int j = 0; j < 8; ++j) { sE[ibase + j] = E[j]; sO[ibase + j] = O[j]; }
    if (lane == 31) sE[256] = Eex;
    __syncwarp();
    if (lane == 0) {
        float vb = sE[Ut];
        float vl = sO[Ut - 1];
        g_nll[b] = -(fmaxf(vb, vl) + Cacc);
    }
#undef SUBSTEP
#undef ISSUE4U
#undef ISSUE4G
}

// ---------------------------------------------------------------------------
// Kernel 3: reduce to scalar loss (fixed-order, deterministic)
// ---------------------------------------------------------------------------
__global__ void __launch_bounds__(32) finalize_kernel(const int* __restrict__ loglen,
                                                      float* __restrict__ out) {
    int lane = threadIdx.x;
    float s = 0.0f, c = 0.0f;
    for (int bb = lane; bb < Bb; bb += 32) { s += g_nll[bb]; c += (float)loglen[bb]; }
#pragma unroll
    for (int o = 16; o; o >>= 1) {
        s += __shfl_xor_sync(0xffffffffu, s, o);
        c += __shfl_xor_sync(0xffffffffu, c, o);
    }
    if (lane == 0) out[0] = s / c;
}

// ---------------------------------------------------------------------------
extern "C" void kernel_launch(void* const* d_in, const int* in_sizes, int n_in,
                              void* d_out, int out_size) {
    const float* logits  = (const float*)d_in[0];
    const int*   targets = (const int*)d_in[1];
    const int*   loglen  = (const int*)d_in[2];
    const int*   tgtlen  = (const int*)d_in[3];

    const int dpSmem = 8 * RINGF * (int)sizeof(float);   // 128 KB
    cudaFuncSetAttribute(dp_kernel, cudaFuncAttributeMaxDynamicSharedMemorySize, dpSmem);

    gather_kernel<<<dim3(Tt / GB_ROWS, Bb), 256>>>(logits, targets, loglen);
    dp_kernel<<<8, 256, dpSmem>>>(targets, loglen, tgtlen);
    finalize_kernel<<<1, 32>>>(loglen, (float*)d_out);
}

// round 7
// speedup vs baseline: 2.7528x; 1.6706x over previous
#include <cuda_runtime.h>
#include <math.h>

#define Bb 64
#define Tt 2048
#define Vv 256
#define Uu 256
#define NEGV (-1e30f)

__device__ float g_d[(size_t)Bb * Tt * 256];   // d[b,t,i] = logits[b,t,tgt[i]] - logits[b,t,0]
__device__ float g_Cpart[Bb * 256];            // per-8-row blank-logp partials
__device__ float g_nll[Bb];

__device__ __forceinline__ void cp16(unsigned sa, const float* g) {
    asm volatile("cp.async.cg.shared.global [%0], [%1], 16;\n" :: "r"(sa), "l"(g) : "memory");
}
__device__ __forceinline__ void cpcommit() {
    asm volatile("cp.async.commit_group;\n" ::: "memory");
}
template<int N> __device__ __forceinline__ void cpwait() {
    asm volatile("cp.async.wait_group %0;\n" :: "n"(N) : "memory");
}
__device__ __forceinline__ void strel(unsigned a, int v) {
    asm volatile("st.release.cta.shared.b32 [%0], %1;" :: "r"(a), "r"(v) : "memory");
}
__device__ __forceinline__ void spinwait(unsigned a, int need) {
    int v;
    do { asm volatile("ld.acquire.cta.shared.b32 %0, [%1];" : "=r"(v) : "r"(a) : "memory"); } while (v < need);
}

// ---------------------------------------------------------------------------
// Kernel 1: fused lse + emission-delta gather + blank-logp partial sums.
// (identical to the 125.7us R4 version: 37.8us)
// ---------------------------------------------------------------------------
#define GB_ROWS 64
__global__ void __launch_bounds__(256) gather_kernel(const float* __restrict__ logits,
                                                     const int*  __restrict__ targets,
                                                     const int*  __restrict__ loglen) {
    __shared__ int   sTgt[Uu];
    __shared__ float sRow[8][4][Vv];

    const int b  = blockIdx.y;
    const int c  = blockIdx.x;
    const int L  = loglen[b];
    const int t0 = c * GB_ROWS;
    if (t0 >= L) return;

    const int tid = threadIdx.x, w = tid >> 5, lane = tid & 31;
    sTgt[tid] = targets[b * Uu + tid];
    __syncthreads();

    const int tbase = t0 + w * 8;
    if (tbase >= L) return;
    int nrows = L - tbase; if (nrows > 8) nrows = 8;

    const float* lg   = logits + ((size_t)b * Tt + tbase) * Vv;
    float*       dOut = g_d    + ((size_t)b * Tt + tbase) * 256;

#pragma unroll
    for (int p = 0; p < 3; ++p) {
        if (p < nrows) {
            unsigned sa = (unsigned)__cvta_generic_to_shared(&sRow[w][p][lane * 8]);
            const float* g = lg + (size_t)p * Vv + lane * 8;
            cp16(sa, g);
            cp16(sa + 16, g + 4);
        }
        cpcommit();
    }

    float cb = 0.0f;
    for (int k = 0; k < nrows; ++k) {
        int pf = k + 3;
        if (pf < nrows) {
            unsigned sa = (unsigned)__cvta_generic_to_shared(&sRow[w][pf & 3][lane * 8]);
            const float* g = lg + (size_t)pf * Vv + lane * 8;
            cp16(sa, g);
            cp16(sa + 16, g + 4);
        }
        cpcommit();
        cpwait<3>();
        __syncwarp();

        const float* r = sRow[w][k & 3];
        float4 v0 = *(const float4*)&r[lane * 4];
        float4 v1 = *(const float4*)&r[128 + lane * 4];
        float s = __expf(v0.x) + __expf(v0.y) + __expf(v0.z) + __expf(v0.w)
                + __expf(v1.x) + __expf(v1.y) + __expf(v1.z) + __expf(v1.w);
#pragma unroll
        for (int o = 16; o; o >>= 1) s += __shfl_xor_sync(0xffffffffu, s, o);
        float lse = __logf(s);
        float r0  = __shfl_sync(0xffffffffu, v0.x, 0);
        cb += r0 - lse;

        int4 tg0 = *(const int4*)&sTgt[lane * 8];
        int4 tg1 = *(const int4*)&sTgt[lane * 8 + 4];
        float4 d0, d1;
        d0.x = r[tg0.x] - r0;  d0.y = r[tg0.y] - r0;
        d0.z = r[tg0.z] - r0;  d0.w = r[tg0.w] - r0;
        d1.x = r[tg1.x] - r0;  d1.y = r[tg1.y] - r0;
        d1.z = r[tg1.z] - r0;  d1.w = r[tg1.w] - r0;

        *(float4*)&dOut[(size_t)k * 256 + lane * 8]     = d0;
        *(float4*)&dOut[(size_t)k * 256 + lane * 8 + 4] = d1;
        __syncwarp();
    }
    if (lane == 0) g_Cpart[b * 256 + (tbase >> 3)] = cb;
}

// ---------------------------------------------------------------------------
// Kernel 2: Viterbi DP, 2 warps per batch with pipeline skew.
//   warp 0: pairs 0..127   (states 0..255)  -- produces boundary O_127(t)
//   warp 1: pairs 128..255 + state 512      -- consumes boundary one chunk late
// Boundary bnd[t+1] = O_127 after step t (full-length array: no backpressure).
// Progress counter released per 32-step chunk (st.release/ld.acquire, lane 31
// releases = same lane that wrote bnd). 4 pairs/lane, early-shuffle step,
// per-warp cp.async ring (32 half-rows, DPG=6) as in R4.
// ---------------------------------------------------------------------------
#define DPGc 6
__global__ void __launch_bounds__(64, 1) dp_kernel(const int* __restrict__ targets,
                                                   const int* __restrict__ loglen,
                                                   const int* __restrict__ tgtlen) {
    __shared__ float sBnd[Tt + 8];
    __shared__ float sRing[2][32 * 128];
    __shared__ float sDump[32];
    __shared__ int   sProg;

    const int tid  = threadIdx.x;
    const int wid  = tid >> 5;
    const int lane = tid & 31;
    const int b    = blockIdx.x;
    const int L    = loglen[b];
    const int Ut   = tgtlen[b];
    const int l4   = lane * 4;
    const int pbase = wid * 128 + l4;            // global pair index base
    const float* __restrict__ emB = g_d + (size_t)b * Tt * 256 + wid * 128;
    float* ring = sRing[wid];
    const unsigned ringB = (unsigned)__cvta_generic_to_shared(ring);
    const unsigned bndB  = (unsigned)__cvta_generic_to_shared(sBnd);
    const unsigned progA = (unsigned)__cvta_generic_to_shared(&sProg);

    if (tid == 0) { sProg = 0; sBnd[0] = NEGV; }
    __syncthreads();

    float gate[4];
    {
        int prev = (pbase == 0) ? -1 : targets[b * Uu + pbase - 1];
#pragma unroll
        for (int j = 0; j < 4; ++j) {
            int cur = targets[b * Uu + pbase + j];
            gate[j] = (pbase + j >= 1 && cur != prev) ? 0.0f : NEGV;
            prev = cur;
        }
    }

    float E[4], O[4];
#pragma unroll
    for (int j = 0; j < 4; ++j) { E[j] = NEGV; O[j] = NEGV; }
    if (tid == 0) E[0] = 0.0f;                   // alpha_hat seed
    float Eex = NEGV, pO_cur = NEGV;
    const float pOmask = (lane == 0) ? NEGV : 0.0f;

    // branch-free boundary store: lane31 -> bnd slot, others -> private dump
    const unsigned stBase = (lane == 31) ? bndB
                           : (unsigned)__cvta_generic_to_shared(&sDump[lane]);
    const unsigned stStep = (lane == 31) ? 4u : 0u;

#define ISSUEG(ROW0)                                                          \
    {                                                                         \
        _Pragma("unroll")                                                     \
        for (int r_ = 0; r_ < 4; ++r_) {                                      \
            int row_ = (ROW0) + r_;                                           \
            if (row_ < L) {                                                   \
                unsigned sa_ = ringB + ((((unsigned)row_ & 31u) << 7) + (unsigned)l4) * 4u; \
                cp16(sa_, emB + (size_t)row_ * 256 + l4);                     \
            }                                                                 \
        }                                                                     \
        cpcommit();                                                           \
    }

    // prologue: groups 0..5 (rows 0..23; L >= 1024)
#pragma unroll
    for (int g2 = 0; g2 < DPGc; ++g2) ISSUEG(g2 * 4);
    cpwait<DPGc - 2>();

    float buf[2][4];
    *(float4*)&buf[0][0] = *(const float4*)(ring + l4);   // row 0

    const int ncfull = L >> 5;
    const int rem32  = L & 31;
    int blk = 0;

#define SUB0(KPAR, T)                                                         \
    {                                                                         \
        const float* sp_ = ring + ((((T) + 1) & 31) << 7) + l4;               \
        *(float4*)&buf[((KPAR) + 1) & 1][0] = *(const float4*)sp_;            \
        const float* dv = buf[(KPAR) & 1];                                    \
        float e3 = E[3], o3 = O[3];                                           \
        float O3n = fmaxf(fmaxf(o3, e3), O[2] + gate[3]) + dv[3];             \
        float E3n = fmaxf(e3, O[2]);                                          \
        float nextPO = __shfl_up_sync(0xffffffffu, O3n, 1);                   \
        unsigned dst_ = stBase + (unsigned)((T) + 1) * stStep;                \
        asm volatile("st.shared.b32 [%0], %1;" :: "r"(dst_), "f"(O3n));       \
        float pO = pO_cur;                                                    \
        _Pragma("unroll")                                                     \
        for (int j = 0; j < 3; ++j) {                                         \
            float e = E[j], o = O[j];                                         \
            E[j] = fmaxf(e, pO);                                              \
            O[j] = fmaxf(fmaxf(o, e), pO + gate[j]) + dv[j];                  \
            pO = o;                                                           \
        }                                                                     \
        E[3] = E3n; O[3] = O3n;                                               \
        pO_cur = nextPO + pOmask;                                             \
    }

#define SUB1(KPAR, T)                                                         \
    {                                                                         \
        const float* sp_ = ring + ((((T) + 1) & 31) << 7) + l4;               \
        *(float4*)&buf[((KPAR) + 1) & 1][0] = *(const float4*)sp_;            \
        float bn = sBnd[(T) + 1];                                             \
        const float* dv = buf[(KPAR) & 1];                                    \
        float e3 = E[3], o3 = O[3];                                           \
        float O3n = fmaxf(fmaxf(o3, e3), O[2] + gate[3]) + dv[3];             \
        float E3n = fmaxf(e3, O[2]);                                          \
        float nextPO = __shfl_up_sync(0xffffffffu, O3n, 1);                   \
        Eex = fmaxf(Eex, o3);                                                 \
        float pO = pO_cur;                                                    \
        _Pragma("unroll")                                                     \
        for (int j = 0; j < 3; ++j) {                                         \
            float e = E[j], o = O[j];                                         \
            E[j] = fmaxf(e, pO);                                              \
            O[j] = fmaxf(fmaxf(o, e), pO + gate[j]) + dv[j];                  \
            pO = o;                                                           \
        }                                                                     \
        E[3] = E3n; O[3] = O3n;                                               \
        pO_cur = (lane == 0) ? bn : nextPO;                                   \
    }

    if (wid == 0) {
        for (int c = 0; c < ncfull; ++c) {
            for (int q = 0; q < 8; ++q, ++blk) {
                ISSUEG((blk + DPGc) * 4);
                cpwait<DPGc - 2>();
                const int t0 = blk * 4;
                SUB0(0, t0); SUB0(1, t0 + 1); SUB0(2, t0 + 2); SUB0(3, t0 + 3);
            }
            if (lane == 31) strel(progA, c + 1);
        }
        const int rb = rem32 >> 2, rr = rem32 & 3;
        for (int q = 0; q < rb; ++q, ++blk) {
            ISSUEG((blk + DPGc) * 4);
            cpwait<DPGc - 2>();
            const int t0 = blk * 4;
            SUB0(0, t0); SUB0(1, t0 + 1); SUB0(2, t0 + 2); SUB0(3, t0 + 3);
        }
        cpwait<0>();
        {
            const int t0 = blk * 4;
            if (rr > 0) SUB0(0, t0);
            if (rr > 1) SUB0(1, t0 + 1);
            if (rr > 2) SUB0(2, t0 + 2);
        }
        if (rem32 && lane == 31) strel(progA, ncfull + 1);
    } else {
        for (int c = 0; c < ncfull; ++c) {
            spinwait(progA, c + 1);
            __syncwarp();
            for (int q = 0; q < 8; ++q, ++blk) {
                ISSUEG((blk + DPGc) * 4);
                cpwait<DPGc - 2>();
                const int t0 = blk * 4;
                SUB1(0, t0); SUB1(1, t0 + 1); SUB1(2, t0 + 2); SUB1(3, t0 + 3);
            }
        }
        if (rem32) {
            spinwait(progA, ncfull + 1);
            __syncwarp();
            const int rb = rem32 >> 2, rr = rem32 & 3;
            for (int q = 0; q < rb; ++q, ++blk) {
                ISSUEG((blk + DPGc) * 4);
                cpwait<DPGc - 2>();
                const int t0 = blk * 4;
                SUB1(0, t0); SUB1(1, t0 + 1); SUB1(2, t0 + 2); SUB1(3, t0 + 3);
            }
            cpwait<0>();
            const int t0 = blk * 4;
            if (rr > 0) SUB1(0, t0);
            if (rr > 1) SUB1(1, t0 + 1);
            if (rr > 2) SUB1(2, t0 + 2);
        } else {
            cpwait<0>();
        }
    }
#undef SUB0
#undef SUB1
#undef ISSUEG

    // blank-logp sum C_b (warp 0, fixed order -> deterministic)
    float Cacc = 0.0f;
    if (wid == 0) {
#pragma unroll
        for (int j = 0; j < 8; ++j) Cacc += g_Cpart[b * 256 + lane * 8 + j];
#pragma unroll
        for (int o2 = 16; o2; o2 >>= 1) Cacc += __shfl_xor_sync(0xffffffffu, Cacc, o2);
    }

    // epilogue: both halves to smem (ring0 is dead for both warps by now)
    float* sE = sRing[0];
    float* sO = sRing[0] + 260;
#pragma unroll
    for (int j = 0; j < 4; ++j) { sE[pbase + j] = E[j]; sO[pbase + j] = O[j]; }
    if (tid == 63) sE[256] = Eex;                // state 512 (E_256), warp1 lane31
    __syncthreads();
    if (tid == 0) {
        float vb = sE[Ut];                       // alpha_hat[2*Ut]
        float vl = sO[Ut - 1];                   // alpha_hat[2*Ut - 1]
        g_nll[b] = -(fmaxf(vb, vl) + Cacc);
    }
}

// ---------------------------------------------------------------------------
// Kernel 3: reduce to scalar loss (fixed-order, deterministic)
// ---------------------------------------------------------------------------
__global__ void __launch_bounds__(32) finalize_kernel(const int* __restrict__ loglen,
                                                      float* __restrict__ out) {
    int lane = threadIdx.x;
    float s = 0.0f, c = 0.0f;
    for (int bb = lane; bb < Bb; bb += 32) { s += g_nll[bb]; c += (float)loglen[bb]; }
#pragma unroll
    for (int o = 16; o; o >>= 1) {
        s += __shfl_xor_sync(0xffffffffu, s, o);
        c += __shfl_xor_sync(0xffffffffu, c, o);
    }
    if (lane == 0) out[0] = s / c;
}

// ---------------------------------------------------------------------------
extern "C" void kernel_launch(void* const* d_in, const int* in_sizes, int n_in,
                              void* d_out, int out_size) {
    const float* logits  = (const float*)d_in[0];
    const int*   targets = (const int*)d_in[1];
    const int*   loglen  = (const int*)d_in[2];
    const int*   tgtlen  = (const int*)d_in[3];

    gather_kernel<<<dim3(Tt / GB_ROWS, Bb), 256>>>(logits, targets, loglen);
    dp_kernel<<<Bb, 64>>>(targets, loglen, tgtlen);
    finalize_kernel<<<1, 32>>>(loglen, (float*)d_out);
}